// round 15
// baseline (speedup 1.0000x reference)
#include <cuda_runtime.h>
#include <cstdint>

#define BB 2
#define SS 2048
#define HH 16
#define DD 64
#define EE 1024
#define MM (BB*SS)        /* 4096 */
#define N3 (3*EE)         /* 3072 */
#define OUTN (MM*EE)      /* 4194304 */

// GEMM fragment-major permuted smem (unchanged from Round-14 WIN)
#define ASZ 4224
#define BSZ 4224
#define GEMM_SMEM_BYTES ((2*ASZ + 2*BSZ) * 4)   /* 67584 B */

// Scratch (allocation-free rule: __device__ globals)
__device__ float g_q[BB*HH*SS*DD];     // q in [B,H,S,D]
__device__ float g_attn[MM*EE];        // attention output, [B,S,E] row-major
__device__ float g_kscr[BB*HH*SS*DD];  // fallback if harness only wants `out`
__device__ float g_vscr[BB*HH*SS*DD];

__device__ __forceinline__ uint32_t f2tf32(float f) {
    uint32_t r;
    asm("cvt.rna.tf32.f32 %0, %1;" : "=r"(r) : "f"(f));
    return r;
}

__device__ __forceinline__ void mma_tf32(float c[4], const uint32_t a[4], const uint32_t b[2]) {
    asm volatile(
        "mma.sync.aligned.m16n8k8.row.col.f32.tf32.tf32.f32 "
        "{%0,%1,%2,%3}, {%4,%5,%6,%7}, {%8,%9}, {%0,%1,%2,%3};"
        : "+f"(c[0]), "+f"(c[1]), "+f"(c[2]), "+f"(c[3])
        : "r"(a[0]), "r"(a[1]), "r"(a[2]), "r"(a[3]), "r"(b[0]), "r"(b[1]));
}

// ---------------------------------------------------------------------------
// tf32 tensor-core GEMM (unchanged from Round-14 passing kernel)
// ---------------------------------------------------------------------------
template<int NDIM, int EPI>
__global__ __launch_bounds__(256, 1) void mma_gemm_kernel(
    const float* __restrict__ A, const float* __restrict__ Bw,
    const float* __restrict__ bias,
    float* __restrict__ out0, float* __restrict__ out1, float* __restrict__ out2)
{
    extern __shared__ uint32_t sm[];   // [A0][A1][B0][B1]

    const int tid  = threadIdx.x;
    const int lane = tid & 31;
    const int warp = tid >> 5;
    const int wm   = warp & 3;
    const int wn   = warp >> 2;
    const int m0   = blockIdx.y * 128;
    const int n0   = blockIdx.x * 128;
    const int lq   = lane >> 2;
    const int lr   = lane & 3;

    float acc[2][8][4];
#pragma unroll
    for (int i = 0; i < 2; i++)
#pragma unroll
        for (int j = 0; j < 8; j++)
#pragma unroll
            for (int t = 0; t < 4; t++) acc[i][j][t] = 0.f;

    float4 pa[4], pb[4];

    auto ldg = [&](int k0) {
#pragma unroll
        for (int i = 0; i < 4; i++) {
            const int idx = i * 256 + tid;
            pa[i] = *(const float4*)&A[(size_t)(m0 + (idx >> 3)) * EE + k0 + ((idx & 7) << 2)];
            pb[i] = *(const float4*)&Bw[(size_t)(k0 + (idx >> 5)) * NDIM + n0 + ((idx & 31) << 2)];
        }
    };
    auto sts = [&](int buf) {
        uint32_t* Ap = sm + buf * ASZ;
        uint32_t* Bp = sm + 2 * ASZ + buf * BSZ;
#pragma unroll
        for (int i = 0; i < 4; i++) {
            const int idx = i * 256 + tid;
            const int am  = idx >> 3, ak4 = (idx & 7) << 2;
            const int gA  = (am >> 4) * 4 + (ak4 >> 3);
            const int sA  = ((am >> 3) & 1) + ((ak4 >> 2) & 1) * 2;
            const int lbA = (am & 7) * 4;
            const float* av = (const float*)&pa[i];
#pragma unroll
            for (int j = 0; j < 4; j++)
                Ap[(gA * 33 + lbA + j) * 4 + sA] = f2tf32(av[j]);
            const int bk  = idx >> 5, bn4 = (idx & 31) << 2;
            const int kk8 = bk >> 3;
            const int slot = (bk >> 2) & 1;
            const int nt  = bn4 >> 3;
            const int hB  = kk8 * 8 + (nt >> 1);
            const int wB  = (nt & 1) * 2 + slot;
            const float* bv = (const float*)&pb[i];
#pragma unroll
            for (int j = 0; j < 4; j++) {
                const int laneB = ((bn4 & 4) + j) * 4 + (bk & 3);
                Bp[(hB * 33 + laneB) * 4 + wB] = f2tf32(bv[j]);
            }
        }
    };

    ldg(0);
    sts(0);
    ldg(32);
    __syncthreads();

    for (int t = 0; t < 32; t++) {
        const int cur = t & 1;
        if (t + 1 < 32) {
            sts(cur ^ 1);
            if (t + 2 < 32) ldg((t + 2) * 32);
        }
        const uint32_t* Asb = sm + cur * ASZ;
        const uint32_t* Bsb = sm + 2 * ASZ + cur * BSZ;

#pragma unroll
        for (int kk8 = 0; kk8 < 4; kk8++) {
            uint32_t af[2][4];
#pragma unroll
            for (int mt = 0; mt < 2; mt++) {
                const int g = (wm * 2 + mt) * 4 + kk8;
                *(uint4*)&af[mt][0] = *(const uint4*)&Asb[(g * 33 + lane) * 4];
            }
            uint32_t bq[4][4];
#pragma unroll
            for (int q = 0; q < 4; q++) {
                const int h = kk8 * 8 + wn * 4 + q;
                *(uint4*)&bq[q][0] = *(const uint4*)&Bsb[(h * 33 + lane) * 4];
            }
#pragma unroll
            for (int mt = 0; mt < 2; mt++)
#pragma unroll
                for (int nt = 0; nt < 8; nt++) {
                    uint32_t bf[2] = { bq[nt >> 1][(nt & 1) * 2],
                                       bq[nt >> 1][(nt & 1) * 2 + 1] };
                    mma_tf32(acc[mt][nt], af[mt], bf);
                }
        }
        __syncthreads();
    }

#pragma unroll
    for (int mt = 0; mt < 2; mt++) {
        const int mA = m0 + wm * 32 + mt * 16 + lq;
        const int mB = mA + 8;
#pragma unroll
        for (int nt = 0; nt < 8; nt++) {
            const int n  = n0 + wn * 64 + nt * 8 + 2 * lr;
            const float bs0 = bias[n], bs1 = bias[n + 1];
            float2 vA = make_float2(acc[mt][nt][0] + bs0, acc[mt][nt][1] + bs1);
            float2 vB = make_float2(acc[mt][nt][2] + bs0, acc[mt][nt][3] + bs1);
            if (EPI == 0) {
                *(float2*)&out0[(size_t)mA * NDIM + n] = vA;
                *(float2*)&out0[(size_t)mB * NDIM + n] = vB;
            } else {
                const int seg = n >> 10;
                const int c   = n & 1023;
                const int h   = c >> 6;
                const int d   = c & 63;
                float* dst = (seg == 0) ? out0 : ((seg == 1) ? out1 : out2);
                const int bA = mA >> 11, sA = mA & 2047;
                const int bB = mB >> 11, sB = mB & 2047;
                *(float2*)&dst[(((size_t)(bA * HH) + h) * SS + sA) * DD + d] = vA;
                *(float2*)&dst[(((size_t)(bB * HH) + h) * SS + sB) * DD + d] = vB;
            }
        }
    }
}

// ---------------------------------------------------------------------------
// tf32 tensor-core flash attention, causal — fragment-major smem.
// Ks: 32 chunks (kk8*4 + ntpair), word (h*33+lane)*4 + w,
//     w = (nt&1)*2 + slot, value K[nt*8+lq][kk8*8+lr+4*slot], lane=lq*4+lr.
// Vs: same chunking, value V[kk8*8+lr+4*slot][nt*8+lq].
// P:  overlaid into this warp's 1056-word slice of Ks after scores are
//     consumed; chunk g=kk8, GEMM-A layout (s = rowhalf + 2*colhalf).
// ---------------------------------------------------------------------------
__global__ __launch_bounds__(128) void attn_mma_kernel(
    const float* __restrict__ Q, const float* __restrict__ K,
    const float* __restrict__ V, float* __restrict__ O)
{
    __shared__ uint32_t Ks[32 * 132];   // 4224 words; P overlay region
    __shared__ uint32_t Vs[32 * 132];

    const int tid  = threadIdx.x;
    const int lane = tid & 31;
    const int warp = tid >> 5;
    const int lq   = lane >> 2;
    const int lr   = lane & 3;
    const int qt = blockIdx.x, h = blockIdx.y, b = blockIdx.z;

    const size_t bho = (size_t)(b * HH + h) * SS * DD;
    const float* Qb = Q + bho;
    const float* Kb = K + bho;
    const float* Vb = V + bho;

    const int q0  = qt * 64 + warp * 16;
    const int qg0 = q0 + lq;        // row A (acc c0,c1)
    const int qg1 = q0 + lq + 8;    // row B (acc c2,c3)

    // Q fragments, pre-scaled by 1/sqrt(64)=0.125, tf32
    uint32_t qa[8][4];
#pragma unroll
    for (int kk8 = 0; kk8 < 8; kk8++) {
        const int d0 = kk8 * 8;
        qa[kk8][0] = f2tf32(Qb[(size_t)qg0 * DD + d0 + lr]     * 0.125f);
        qa[kk8][1] = f2tf32(Qb[(size_t)qg1 * DD + d0 + lr]     * 0.125f);
        qa[kk8][2] = f2tf32(Qb[(size_t)qg0 * DD + d0 + lr + 4] * 0.125f);
        qa[kk8][3] = f2tf32(Qb[(size_t)qg1 * DD + d0 + lr + 4] * 0.125f);
    }

    float oacc[8][4];
#pragma unroll
    for (int nt = 0; nt < 8; nt++)
#pragma unroll
        for (int t = 0; t < 4; t++) oacc[nt][t] = 0.f;
    float m0 = -1e30f, m1 = -1e30f, l0 = 0.f, l1 = 0.f;

    for (int kt = 0; kt <= qt; kt++) {
        __syncthreads();   // prior tile's PV reads of Ks(P)/Vs are done
        // load K/V tile with fragment-major scatter
#pragma unroll
        for (int i = 0; i < 8; i++) {
            const int idx = i * 128 + tid;        // 0..1023 float4 slots
            const int row = idx >> 4;             // key index 0..63
            const int c4  = (idx & 15) << 2;      // dim base 0..60
            float4 kv = *(const float4*)&Kb[(size_t)(kt * 64 + row) * DD + c4];
            float4 vv = *(const float4*)&Vb[(size_t)(kt * 64 + row) * DD + c4];
            const float* kp = (const float*)&kv;
            const float* vp = (const float*)&vv;
            // K scatter: h=(c4>>3)*4+(row>>4), w=((row>>3)&1)*2+((c4>>2)&1), lane=(row&7)*4+j
            const int hK = (c4 >> 3) * 4 + (row >> 4);
            const int wK = ((row >> 3) & 1) * 2 + ((c4 >> 2) & 1);
            const int lK = (row & 7) * 4;
#pragma unroll
            for (int j = 0; j < 4; j++)
                Ks[(hK * 33 + lK + j) * 4 + wK] = f2tf32(kp[j]);
            // V scatter: h=(row>>3)*4+(c4>>4), w=((c4>>3)&1)*2+((row>>2)&1), lane=((c4&7)+j)*4+(row&3)
            const int hV = (row >> 3) * 4 + (c4 >> 4);
            const int wV = ((c4 >> 3) & 1) * 2 + ((row >> 2) & 1);
            const int lVb = (c4 & 7);
            const int lrV = row & 3;
#pragma unroll
            for (int j = 0; j < 4; j++)
                Vs[(hV * 33 + (lVb + j) * 4 + lrV) * 4 + wV] = f2tf32(vp[j]);
        }
        __syncthreads();

        // --- scores: S = (Q*scale) . K^T ---
        float sacc[8][4];
#pragma unroll
        for (int nt = 0; nt < 8; nt++)
#pragma unroll
            for (int t = 0; t < 4; t++) sacc[nt][t] = 0.f;
#pragma unroll
        for (int kk8 = 0; kk8 < 8; kk8++) {
            uint32_t bq[4][4];
#pragma unroll
            for (int q = 0; q < 4; q++)
                *(uint4*)&bq[q][0] = *(const uint4*)&Ks[((kk8 * 4 + q) * 33 + lane) * 4];
#pragma unroll
            for (int nt = 0; nt < 8; nt++) {
                uint32_t bf[2] = { bq[nt >> 1][(nt & 1) * 2],
                                   bq[nt >> 1][(nt & 1) * 2 + 1] };
                mma_tf32(sacc[nt], qa[kk8], bf);
            }
        }

        // --- causal mask + row max ---
        float rmax0 = m0, rmax1 = m1;
#pragma unroll
        for (int nt = 0; nt < 8; nt++) {
            const int gk = kt * 64 + nt * 8 + 2 * lr;
            if (gk     > qg0) sacc[nt][0] = -1e30f;
            if (gk + 1 > qg0) sacc[nt][1] = -1e30f;
            if (gk     > qg1) sacc[nt][2] = -1e30f;
            if (gk + 1 > qg1) sacc[nt][3] = -1e30f;
            rmax0 = fmaxf(rmax0, fmaxf(sacc[nt][0], sacc[nt][1]));
            rmax1 = fmaxf(rmax1, fmaxf(sacc[nt][2], sacc[nt][3]));
        }
        rmax0 = fmaxf(rmax0, __shfl_xor_sync(0xffffffffu, rmax0, 1));
        rmax0 = fmaxf(rmax0, __shfl_xor_sync(0xffffffffu, rmax0, 2));
        rmax1 = fmaxf(rmax1, __shfl_xor_sync(0xffffffffu, rmax1, 1));
        rmax1 = fmaxf(rmax1, __shfl_xor_sync(0xffffffffu, rmax1, 2));

        const float a0 = __expf(m0 - rmax0);
        const float a1 = __expf(m1 - rmax1);
        m0 = rmax0; m1 = rmax1;

        float ls0 = 0.f, ls1 = 0.f;
#pragma unroll
        for (int nt = 0; nt < 8; nt++) {
            sacc[nt][0] = __expf(sacc[nt][0] - m0);
            sacc[nt][1] = __expf(sacc[nt][1] - m0);
            sacc[nt][2] = __expf(sacc[nt][2] - m1);
            sacc[nt][3] = __expf(sacc[nt][3] - m1);
            ls0 += sacc[nt][0] + sacc[nt][1];
            ls1 += sacc[nt][2] + sacc[nt][3];
        }
        ls0 += __shfl_xor_sync(0xffffffffu, ls0, 1);
        ls0 += __shfl_xor_sync(0xffffffffu, ls0, 2);
        ls1 += __shfl_xor_sync(0xffffffffu, ls1, 1);
        ls1 += __shfl_xor_sync(0xffffffffu, ls1, 2);
        l0 = l0 * a0 + ls0;
        l1 = l1 * a1 + ls1;

#pragma unroll
        for (int nt = 0; nt < 8; nt++) {
            oacc[nt][0] *= a0; oacc[nt][1] *= a0;
            oacc[nt][2] *= a1; oacc[nt][3] *= a1;
        }

        __syncthreads();   // all warps done reading Ks -> safe to overwrite with P

        // write P into this warp's overlay slice, A-chunk layout (g = nt)
        uint32_t* Pw = &Ks[warp * 1056];
#pragma unroll
        for (int nt = 0; nt < 8; nt++) {
            // a0 = (g*33 + lane0)*4 + sbase; lane0 = lq*4+2*(lr&1); sbase = 2*(lr>>1)
            const int a0 = (nt * 33 + lq * 4 + 2 * (lr & 1)) * 4 + 2 * (lr >> 1);
            uint2 w0 = make_uint2(f2tf32(sacc[nt][0]), f2tf32(sacc[nt][2]));  // s, s+1
            uint2 w1 = make_uint2(f2tf32(sacc[nt][1]), f2tf32(sacc[nt][3]));
            *(uint2*)&Pw[a0]     = w0;   // col 2lr   : rows lq, lq+8
            *(uint2*)&Pw[a0 + 4] = w1;   // col 2lr+1 : rows lq, lq+8
        }
        __syncwarp();

        // --- O += P . V ---
#pragma unroll
        for (int kk8 = 0; kk8 < 8; kk8++) {
            uint32_t af[4];
            *(uint4*)&af[0] = *(const uint4*)&Pw[(kk8 * 33 + lane) * 4];
            uint32_t bqv[4][4];
#pragma unroll
            for (int q = 0; q < 4; q++)
                *(uint4*)&bqv[q][0] = *(const uint4*)&Vs[((kk8 * 4 + q) * 33 + lane) * 4];
#pragma unroll
            for (int nt = 0; nt < 8; nt++) {
                uint32_t bf[2] = { bqv[nt >> 1][(nt & 1) * 2],
                                   bqv[nt >> 1][(nt & 1) * 2 + 1] };
                mma_tf32(oacc[nt], af, bf);
            }
        }
    }

    // epilogue: normalize, write [B,S,E] row-major for the proj GEMM
    const float inv0 = 1.f / l0;
    const float inv1 = 1.f / l1;
    const size_t r0 = (size_t)(b * SS + qg0) * EE + h * 64;
    const size_t r1 = (size_t)(b * SS + qg1) * EE + h * 64;
#pragma unroll
    for (int nt = 0; nt < 8; nt++) {
        float2 v0 = make_float2(oacc[nt][0] * inv0, oacc[nt][1] * inv0);
        float2 v1 = make_float2(oacc[nt][2] * inv1, oacc[nt][3] * inv1);
        *(float2*)&O[r0 + nt * 8 + 2 * lr] = v0;
        *(float2*)&O[r1 + nt * 8 + 2 * lr] = v1;
    }
}

// ---------------------------------------------------------------------------
extern "C" void kernel_launch(void* const* d_in, const int* in_sizes, int n_in,
                              void* d_out, int out_size)
{
    const float* x      = (const float*)d_in[0];
    const float* qkv_w  = (const float*)d_in[1];
    const float* qkv_b  = (const float*)d_in[2];
    const float* proj_w = (const float*)d_in[3];
    const float* proj_b = (const float*)d_in[4];
    float* out = (float*)d_out;

    float *qbuf, *attnbuf, *kscr, *vscr;
    cudaGetSymbolAddress((void**)&qbuf,    g_q);
    cudaGetSymbolAddress((void**)&attnbuf, g_attn);
    cudaGetSymbolAddress((void**)&kscr,    g_kscr);
    cudaGetSymbolAddress((void**)&vscr,    g_vscr);

    const bool kv_in_out = (out_size >= 3*OUTN);
    float* kdst = kv_in_out ? (out + OUTN)   : kscr;
    float* vdst = kv_in_out ? (out + 2*OUTN) : vscr;

    cudaFuncSetAttribute(mma_gemm_kernel<N3, 1>,
                         cudaFuncAttributeMaxDynamicSharedMemorySize, GEMM_SMEM_BYTES);
    cudaFuncSetAttribute(mma_gemm_kernel<EE, 0>,
                         cudaFuncAttributeMaxDynamicSharedMemorySize, GEMM_SMEM_BYTES);

    mma_gemm_kernel<N3, 1><<<dim3(N3/128, MM/128), 256, GEMM_SMEM_BYTES>>>(
        x, qkv_w, qkv_b, qbuf, kdst, vdst);
    attn_mma_kernel<<<dim3(SS/64, HH, BB), 128>>>(qbuf, kdst, vdst, attnbuf);
    mma_gemm_kernel<EE, 0><<<dim3(EE/128, MM/128), 256, GEMM_SMEM_BYTES>>>(
        attnbuf, proj_w, proj_b, out, nullptr, nullptr);
}